// round 5
// baseline (speedup 1.0000x reference)
#include <cuda_runtime.h>
#include <cstdint>

#define NVOX (64*64*64)        // 262144 voxels
#define BKN 28                 // 4 batches * 7 moving parts
#define CHUNKS 32              // partial-reduction chunks per (b,k)
#define NBLOCKS (BKN * CHUNKS) // 896 reduce blocks
#define RED_THREADS 256
#define APPLY_THREADS 256

// Scratch (no allocations allowed)
__device__ float    g_partial[NBLOCKS * 4];
__device__ float    g_coef[BKN * 12];     // [0..8]=M=R-I row-major, [9..11]=d
__device__ unsigned g_count = 0;          // self-resets every launch

// ---------------- PTX helpers ----------------
__device__ __forceinline__ uint32_t smem_u32(const void* p) {
    uint32_t a;
    asm("{ .reg .u64 t; cvta.to.shared.u64 t, %1; cvt.u32.u64 %0, t; }"
        : "=r"(a) : "l"(p));
    return a;
}
__device__ __forceinline__ void mbar_init(uint32_t mbar, uint32_t count) {
    asm volatile("mbarrier.init.shared.b64 [%0], %1;" :: "r"(mbar), "r"(count) : "memory");
}
__device__ __forceinline__ void mbar_expect_tx(uint32_t mbar, uint32_t bytes) {
    asm volatile("mbarrier.arrive.expect_tx.shared.b64 _, [%0], %1;"
                 :: "r"(mbar), "r"(bytes) : "memory");
}
__device__ __forceinline__ void mbar_wait0(uint32_t mbar) {
    asm volatile(
        "{\n\t.reg .pred P;\n\t"
        "W_%=:\n\t"
        "mbarrier.try_wait.parity.shared::cta.b64 P, [%0], 0;\n\t"
        "@!P bra W_%=;\n\t}"
        :: "r"(mbar) : "memory");
}
__device__ __forceinline__ void bulk_copy(uint32_t dst_smem, const void* src_gmem,
                                          uint32_t bytes, uint32_t mbar) {
    asm volatile(
        "cp.async.bulk.shared::cta.global.mbarrier::complete_tx::bytes [%0], [%1], %2, [%3];"
        :: "r"(dst_smem), "l"(src_gmem), "r"(bytes), "r"(mbar) : "memory");
}
__device__ __forceinline__ void fence_async_shared() {
    asm volatile("fence.proxy.async.shared::cta;" ::: "memory");
}

// ---------------------------------------------------------------------------
// Pass 1: per-(b,k) weighted sums (sum m, sum m*gx, sum m*gy, sum m*gz).
// Each block bulk-copies its 32 KB chunk into smem via TMA (no register
// pressure, deep chip-level MLP), then reduces from smem. The LAST block
// folds all partials into coefficients: M = R - I, d = p + t - R p.
// ---------------------------------------------------------------------------
__global__ void __launch_bounds__(RED_THREADS)
reduce_k(const float* __restrict__ mask, const float* __restrict__ grids,
         const float* __restrict__ trans_vec, const float* __restrict__ rot_mat)
{
    const int bk    = blockIdx.x >> 5;     // / CHUNKS
    const int chunk = blockIdx.x & 31;     // % CHUNKS
    const int b = bk / 7, k = bk % 7;
    const int tid = threadIdx.x;

    __shared__ __align__(16) float buf[8192];   // 32 KB chunk
    __shared__ float ax[64], ay[64], az[64];
    __shared__ float red[8][4];
    __shared__ float fold[BKN][4];
    __shared__ __align__(8) unsigned long long mbar;
    __shared__ bool  is_last;

    const uint32_t mb = smem_u32(&mbar);
    if (tid == 0) mbar_init(mb, 1);
    if (tid < 64) {
        ax[tid] = grids[tid << 12];                 // gx[i,0,0]
        ay[tid] = grids[NVOX + (tid << 6)];         // gy[0,j,0]
        az[tid] = grids[2 * NVOX + tid];            // gz[0,0,k]
    }
    __syncthreads();                                 // mbar init visible

    const float* src = mask + ((size_t)(b * 8 + k)) * NVOX + (size_t)chunk * 8192;
    if (tid == 0) {
        fence_async_shared();
        mbar_expect_tx(mb, 32768);
        bulk_copy(smem_u32(buf), src, 32768, mb);
    }
    mbar_wait0(mb);

    const int vbase = chunk * (NVOX / CHUNKS);
    const float4* b4 = (const float4*)buf;

    float s0 = 0.f, sx = 0.f, sy = 0.f, sz = 0.f;
#pragma unroll
    for (int t = 0; t < 8; ++t) {
        const int idx4 = t * RED_THREADS + tid;
        const float4 m = b4[idx4];                  // conflict-free LDS.128
        const int v  = vbase + (idx4 << 2);
        const int i  = v >> 12;
        const int j  = (v >> 6) & 63;
        const int kk = v & 63;
        const float ms = (m.x + m.y) + (m.z + m.w);
        s0 += ms;
        sx = fmaf(ax[i], ms, sx);
        sy = fmaf(ay[j], ms, sy);
        sz = fmaf(az[kk],     m.x,
             fmaf(az[kk + 1], m.y,
             fmaf(az[kk + 2], m.z,
             fmaf(az[kk + 3], m.w, sz))));
    }

    // warp tree reduce (deterministic)
#pragma unroll
    for (int off = 16; off; off >>= 1) {
        s0 += __shfl_down_sync(0xFFFFFFFFu, s0, off);
        sx += __shfl_down_sync(0xFFFFFFFFu, sx, off);
        sy += __shfl_down_sync(0xFFFFFFFFu, sy, off);
        sz += __shfl_down_sync(0xFFFFFFFFu, sz, off);
    }
    const int w = tid >> 5, l = tid & 31;
    if (l == 0) { red[w][0] = s0; red[w][1] = sx; red[w][2] = sy; red[w][3] = sz; }
    __syncthreads();
    if (tid == 0) {
        float r0 = 0.f, r1 = 0.f, r2 = 0.f, r3 = 0.f;
#pragma unroll
        for (int i = 0; i < 8; ++i) {
            r0 += red[i][0]; r1 += red[i][1]; r2 += red[i][2]; r3 += red[i][3];
        }
        float* p = g_partial + blockIdx.x * 4;
        p[0] = r0; p[1] = r1; p[2] = r2; p[3] = r3;
        __threadfence();                                // publish partial
        const unsigned arrived = atomicAdd(&g_count, 1u);
        is_last = (arrived == NBLOCKS - 1);
        if (is_last) g_count = 0;                       // reset for next replay
    }
    __syncthreads();
    if (!is_last) return;

    // -------- last block: fold partials -> coefficients (L2-hot) --------
    if (tid < BKN * 4) {                 // 112 threads: one (bk, component) each
        const int fbk  = tid >> 2;
        const int comp = tid & 3;
        const float* p = g_partial + (fbk * CHUNKS) * 4 + comp;
        float s = 0.f;
#pragma unroll
        for (int c = 0; c < CHUNKS; ++c)
            s += __ldcg(p + c * 4);
        fold[fbk][comp] = s;
    }
    __syncthreads();
    if (tid < BKN) {
        const float inv = 1.f / fold[tid][0];
        const float pv[3] = { fold[tid][1] * inv, fold[tid][2] * inv, fold[tid][3] * inv };
        const float* R = rot_mat   + tid * 9;
        const float* t = trans_vec + tid * 3;
        float* c = g_coef + tid * 12;
#pragma unroll
        for (int r = 0; r < 3; ++r) {
            const float Rp = R[r * 3] * pv[0] + R[r * 3 + 1] * pv[1] + R[r * 3 + 2] * pv[2];
            c[r * 3 + 0] = R[r * 3 + 0] - (r == 0 ? 1.f : 0.f);
            c[r * 3 + 1] = R[r * 3 + 1] - (r == 1 ? 1.f : 0.f);
            c[r * 3 + 2] = R[r * 3 + 2] - (r == 2 ? 1.f : 0.f);
            c[9 + r]     = pv[r] + t[r] - Rp;
        }
    }
}

// ---------------------------------------------------------------------------
// Pass 2: motion[b,c,v] = sum_{k<7} mask[b,k,v] * (M_bk[c,:].g_v + d_bk[c]).
// Each block bulk-copies its 7 x 4 KB mask slices into smem (L2-hot from
// pass 1), then computes and writes 3 x 4 KB of output.
// ---------------------------------------------------------------------------
__global__ void __launch_bounds__(APPLY_THREADS)
apply_k(const float* __restrict__ mask, const float* __restrict__ grids,
        float* __restrict__ out)
{
    const int blocksPerB = NVOX / 4 / APPLY_THREADS;   // 256
    const int b   = blockIdx.x / blocksPerB;
    const int blk = blockIdx.x % blocksPerB;
    const int tid = threadIdx.x;

    __shared__ __align__(16) float buf[7 * 1024];      // 28 KB: 7 mask slices
    __shared__ float cf[84];
    __shared__ float ax[64], ay[64], az[64];
    __shared__ __align__(8) unsigned long long mbar;

    const uint32_t mb = smem_u32(&mbar);
    if (tid == 0) mbar_init(mb, 1);
    if (tid < 84) cf[tid] = g_coef[b * 84 + tid];
    if (tid < 64) {
        ax[tid] = grids[tid << 12];
        ay[tid] = grids[NVOX + (tid << 6)];
        az[tid] = grids[2 * NVOX + tid];
    }
    __syncthreads();                                   // mbar init + cf/axes visible

    const float* srcb = mask + ((size_t)b * 8) * NVOX + (size_t)blk * 1024;
    if (tid == 0) {
        fence_async_shared();
        mbar_expect_tx(mb, 7 * 4096);
#pragma unroll
        for (int k = 0; k < 7; ++k)
            bulk_copy(smem_u32(buf) + k * 4096, srcb + (size_t)k * NVOX, 4096, mb);
    }
    mbar_wait0(mb);

    const int idx4 = blk * APPLY_THREADS + tid;
    const int v  = idx4 << 2;
    const int i  = v >> 12;
    const int j  = (v >> 6) & 63;
    const int kk = v & 63;
    const float gx = ax[i], gy = ay[j];
    const float gz[4] = { az[kk], az[kk + 1], az[kk + 2], az[kk + 3] };

    const float4* b4 = (const float4*)buf;
    float mot[3][4] = {};
#pragma unroll
    for (int k = 0; k < 7; ++k) {
        const float4 m = b4[k * 256 + tid];
        const float mvv[4] = { m.x, m.y, m.z, m.w };
        const float* c = cf + k * 12;
#pragma unroll
        for (int cc = 0; cc < 3; ++cc) {
            const float m2   = c[cc * 3 + 2];
            const float base = fmaf(c[cc * 3], gx, fmaf(c[cc * 3 + 1], gy, c[9 + cc]));
#pragma unroll
            for (int t = 0; t < 4; ++t)
                mot[cc][t] = fmaf(mvv[t], fmaf(m2, gz[t], base), mot[cc][t]);
        }
    }

    float4* o4 = (float4*)out;
#pragma unroll
    for (int cc = 0; cc < 3; ++cc) {
        float4 o = { mot[cc][0], mot[cc][1], mot[cc][2], mot[cc][3] };
        o4[((size_t)b * 3 + cc) * (NVOX / 4) + idx4] = o;
    }
}

// ---------------------------------------------------------------------------
extern "C" void kernel_launch(void* const* d_in, const int* in_sizes, int n_in,
                              void* d_out, int out_size)
{
    const float* mask = nullptr;
    const float* tv   = nullptr;
    const float* rm   = nullptr;
    const float* gr   = nullptr;
    for (int i = 0; i < n_in; ++i) {
        switch (in_sizes[i]) {
            case 8388608: mask = (const float*)d_in[i]; break;   // (4,8,64,64,64)
            case 84:      tv   = (const float*)d_in[i]; break;   // (4,7,3)
            case 252:     rm   = (const float*)d_in[i]; break;   // (4,7,3,3)
            case 786432:  gr   = (const float*)d_in[i]; break;   // (3,64,64,64)
        }
    }
    reduce_k<<<NBLOCKS, RED_THREADS>>>(mask, gr, tv, rm);
    apply_k<<<4 * (NVOX / 4 / APPLY_THREADS), APPLY_THREADS>>>(mask, gr, (float*)d_out);
}